// round 2
// baseline (speedup 1.0000x reference)
#include <cuda_runtime.h>
#include <cstdint>

#define D        128
#define D4       32          // D / 4
#define MAXN     100000
#define TILE_M   64

// Scratch (allocation-free rule: __device__ globals).
__device__ float g_K[(size_t)MAXN * D];
__device__ float g_Q[(size_t)MAXN * D];
__device__ float g_V[(size_t)MAXN * D];
__device__ int   g_is64;

// ---------------------------------------------------------------------------
// Detect edge_index dtype at runtime. int64 little-endian with values < 2^32
// has all odd 32-bit words == 0; int32 data has random indices there.
// ---------------------------------------------------------------------------
__global__ void detect_dtype_kernel(const int* __restrict__ raw)
{
    int ok64 = 1;
    #pragma unroll
    for (int i = 1; i < 256; i += 2)
        if (raw[i] != 0) { ok64 = 0; break; }
    g_is64 = ok64;
}

// ---------------------------------------------------------------------------
// GEMM: out[m][n] = sum_kk x[m][kk] * W[kk][n] + b[n]
// grid.x = node tiles of 64, grid.y = which matrix (0=K,1=Q,2=V,3=skip->d_out)
// 256 threads: 8 m-groups x 32 n-groups; each thread: 8 nodes x 4 outputs.
// ---------------------------------------------------------------------------
__global__ void __launch_bounds__(256) gemm4_kernel(
    const float* __restrict__ x, int N,
    const float* __restrict__ Wk, const float* __restrict__ bk,
    const float* __restrict__ Wq, const float* __restrict__ bq,
    const float* __restrict__ Wv, const float* __restrict__ bv,
    const float* __restrict__ Wsk, const float* __restrict__ bsk,
    float* __restrict__ out)
{
    extern __shared__ float sm[];
    float* Wsh = sm;             // 128*128 floats = 64KB
    float* xsh = sm + D * D;     // 64*128 floats  = 32KB

    const float* W;
    const float* b;
    float* dst;
    switch (blockIdx.y) {
        case 0:  W = Wk;  b = bk;  dst = g_K; break;
        case 1:  W = Wq;  b = bq;  dst = g_Q; break;
        case 2:  W = Wv;  b = bv;  dst = g_V; break;
        default: W = Wsk; b = bsk; dst = out; break;
    }

    const int tid = threadIdx.x;
    const int m0  = blockIdx.x * TILE_M;

    // Load W (16384 floats = 4096 float4; 16 per thread)
    {
        const float4* W4  = (const float4*)W;
        float4*       Ws4 = (float4*)Wsh;
        #pragma unroll
        for (int i = 0; i < 16; i++) Ws4[tid + 256 * i] = W4[tid + 256 * i];
    }
    // Load x tile (64*128 floats = 2048 float4; 8 per thread), zero-pad tail
    {
        const float4* x4  = (const float4*)(x + (size_t)m0 * D);
        float4*       xs4 = (float4*)xsh;
        const int rem = N - m0;
        if (rem >= TILE_M) {
            #pragma unroll
            for (int i = 0; i < 8; i++) xs4[tid + 256 * i] = x4[tid + 256 * i];
        } else {
            #pragma unroll
            for (int i = 0; i < 8; i++) {
                int idx  = tid + 256 * i;
                int node = idx >> 5;  // 32 float4 per row
                float4 z = make_float4(0.f, 0.f, 0.f, 0.f);
                if (node < rem) z = x4[idx];
                xs4[idx] = z;
            }
        }
    }
    __syncthreads();

    const int ng = tid & 31;   // output column group: cols [4*ng, 4*ng+3]
    const int mg = tid >> 5;   // node sub-index: nodes mg, mg+8, ..., mg+56

    float4 acc[8];
    #pragma unroll
    for (int i = 0; i < 8; i++) acc[i] = make_float4(0.f, 0.f, 0.f, 0.f);

    const float4* Ws4 = (const float4*)Wsh;

    #pragma unroll 2
    for (int kk = 0; kk < D; kk += 4) {
        float4 w0 = Ws4[(kk + 0) * D4 + ng];
        float4 w1 = Ws4[(kk + 1) * D4 + ng];
        float4 w2 = Ws4[(kk + 2) * D4 + ng];
        float4 w3 = Ws4[(kk + 3) * D4 + ng];
        #pragma unroll
        for (int i = 0; i < 8; i++) {
            float4 xv = *(const float4*)&xsh[(mg + 8 * i) * D + kk];
            acc[i].x += xv.x * w0.x; acc[i].y += xv.x * w0.y;
            acc[i].z += xv.x * w0.z; acc[i].w += xv.x * w0.w;
            acc[i].x += xv.y * w1.x; acc[i].y += xv.y * w1.y;
            acc[i].z += xv.y * w1.z; acc[i].w += xv.y * w1.w;
            acc[i].x += xv.z * w2.x; acc[i].y += xv.z * w2.y;
            acc[i].z += xv.z * w2.z; acc[i].w += xv.z * w2.w;
            acc[i].x += xv.w * w3.x; acc[i].y += xv.w * w3.y;
            acc[i].z += xv.w * w3.z; acc[i].w += xv.w * w3.w;
        }
    }

    const float4 bb = ((const float4*)b)[ng];
    #pragma unroll
    for (int i = 0; i < 8; i++) {
        int node = m0 + mg + 8 * i;
        if (node < N) {
            float4 r;
            r.x = acc[i].x + bb.x; r.y = acc[i].y + bb.y;
            r.z = acc[i].z + bb.z; r.w = acc[i].w + bb.w;
            ((float4*)dst)[(size_t)node * D4 + ng] = r;
        }
    }
}

// ---------------------------------------------------------------------------
// Edge kernel: one warp per edge. lane c handles channels [4c, 4c+3].
// out[dst] += sigmoid(k[dst] + q[src]) * v[src]  (vector red.global.add)
// ---------------------------------------------------------------------------
__global__ void __launch_bounds__(256) edge_kernel(
    const void* __restrict__ ei_raw, int E, float* __restrict__ out)
{
    const int warp = (blockIdx.x * blockDim.x + threadIdx.x) >> 5;
    const int lane = threadIdx.x & 31;
    if (warp >= E) return;

    int src, dst;
    if (g_is64) {
        const long long* e64 = (const long long*)ei_raw;
        src = (int)e64[warp];
        dst = (int)e64[(size_t)E + warp];
    } else {
        const int* e32 = (const int*)ei_raw;
        src = e32[warp];
        dst = e32[(size_t)E + warp];
    }

    const float4 kd = ((const float4*)g_K)[(size_t)dst * D4 + lane];
    const float4 qs = ((const float4*)g_Q)[(size_t)src * D4 + lane];
    const float4 vs = ((const float4*)g_V)[(size_t)src * D4 + lane];

    float4 m;
    m.x = vs.x * __fdividef(1.f, 1.f + __expf(-(kd.x + qs.x)));
    m.y = vs.y * __fdividef(1.f, 1.f + __expf(-(kd.y + qs.y)));
    m.z = vs.z * __fdividef(1.f, 1.f + __expf(-(kd.z + qs.z)));
    m.w = vs.w * __fdividef(1.f, 1.f + __expf(-(kd.w + qs.w)));

    float* p = out + (size_t)dst * D + lane * 4;
    asm volatile("red.global.add.v4.f32 [%0], {%1, %2, %3, %4};"
                 :: "l"(p), "f"(m.x), "f"(m.y), "f"(m.z), "f"(m.w)
                 : "memory");
}

// ---------------------------------------------------------------------------
extern "C" void kernel_launch(void* const* d_in, const int* in_sizes, int n_in,
                              void* d_out, int out_size)
{
    const float* x    = (const float*)d_in[0];
    const void*  ei   = d_in[1];
    // d_in[2] = edge_attr (unused, zeros)
    const float* Wk   = (const float*)d_in[3];
    const float* bk   = (const float*)d_in[4];
    const float* Wq   = (const float*)d_in[5];
    const float* bq   = (const float*)d_in[6];
    const float* Wv   = (const float*)d_in[7];
    const float* bv   = (const float*)d_in[8];
    const float* Wsk  = (const float*)d_in[9];
    const float* bias = (const float*)d_in[10];
    float* out = (float*)d_out;

    const int N = in_sizes[0] / D;
    const int E = in_sizes[1] / 2;

    detect_dtype_kernel<<<1, 1>>>((const int*)ei);

    const int smem_bytes = (D * D + TILE_M * D) * (int)sizeof(float);  // 96KB
    cudaFuncSetAttribute(gemm4_kernel,
                         cudaFuncAttributeMaxDynamicSharedMemorySize,
                         smem_bytes);

    dim3 ggrid((N + TILE_M - 1) / TILE_M, 4);
    gemm4_kernel<<<ggrid, 256, smem_bytes>>>(
        x, N, Wk, bk, Wq, bq, Wv, bv, Wsk, bias, out);

    const int warps_per_block = 8;                       // 256 threads
    const int eblocks = (E + warps_per_block - 1) / warps_per_block;
    edge_kernel<<<eblocks, 256>>>(ei, E, out);
}

// round 4
// speedup vs baseline: 1.3350x; 1.3350x over previous
#include <cuda_runtime.h>
#include <cuda_bf16.h>
#include <cstdint>

#define D        128
#define D4       32
#define MAXN     100000
#define TILE_M   128
#define ASTRIDE  136   // bf16 elements per smem row (272B, 16B-aligned, conflict-shifted)

// Scratch (allocation-free rule: __device__ globals).
__device__ float g_K[(size_t)MAXN * D];
__device__ float g_Q[(size_t)MAXN * D];
__device__ float g_V[(size_t)MAXN * D];
__device__ int   g_is64;

// smem layout in bf16 elements
#define SM_A_HI  0
#define SM_A_LO  (128 * ASTRIDE)
#define SM_B_HI  (2 * 128 * ASTRIDE)
#define SM_B_LO  (3 * 128 * ASTRIDE)
#define SM_ELEMS (4 * 128 * ASTRIDE)
#define SM_BYTES (SM_ELEMS * 2)

__device__ __forceinline__ uint32_t smem_u32(const void* p) {
    uint32_t a;
    asm("{ .reg .u64 t; cvta.to.shared.u64 t, %1; cvt.u32.u64 %0, t; }"
        : "=r"(a) : "l"(p));
    return a;
}
__device__ __forceinline__ uint32_t pack2(float a, float b) {
    __nv_bfloat162 t = __floats2bfloat162_rn(a, b);
    return *reinterpret_cast<uint32_t*>(&t);
}
__device__ __forceinline__ float bf16_residual(float v) {
    return v - __bfloat162float(__float2bfloat16_rn(v));
}

__device__ __forceinline__ void ldsm_x4(uint32_t* r, uint32_t addr) {
    asm volatile("ldmatrix.sync.aligned.m8n8.x4.shared.b16 {%0,%1,%2,%3}, [%4];"
                 : "=r"(r[0]), "=r"(r[1]), "=r"(r[2]), "=r"(r[3]) : "r"(addr));
}
__device__ __forceinline__ void ldsm_x2(uint32_t* r, uint32_t addr) {
    asm volatile("ldmatrix.sync.aligned.m8n8.x2.shared.b16 {%0,%1}, [%2];"
                 : "=r"(r[0]), "=r"(r[1]) : "r"(addr));
}
__device__ __forceinline__ void mma16816(float* c, const uint32_t* a, const uint32_t* b) {
    asm volatile(
        "mma.sync.aligned.m16n8k16.row.col.f32.bf16.bf16.f32 "
        "{%0,%1,%2,%3}, {%4,%5,%6,%7}, {%8,%9}, {%0,%1,%2,%3};"
        : "+f"(c[0]), "+f"(c[1]), "+f"(c[2]), "+f"(c[3])
        : "r"(a[0]), "r"(a[1]), "r"(a[2]), "r"(a[3]), "r"(b[0]), "r"(b[1]));
}

// ---------------------------------------------------------------------------
// dtype detection for edge_index (int64 little-endian vs int32)
// ---------------------------------------------------------------------------
__global__ void detect_dtype_kernel(const int* __restrict__ raw)
{
    int ok64 = 1;
    #pragma unroll
    for (int i = 1; i < 256; i += 2)
        if (raw[i] != 0) { ok64 = 0; break; }
    g_is64 = ok64;
}

// ---------------------------------------------------------------------------
// HMMA GEMM: out[m][:] = x[m][:] @ W + b, bf16 hi/lo split (3 passes).
// grid.x = node tiles of 128, grid.y = matrix (0=K,1=Q,2=V,3=skip->d_out)
// 8 warps: 2 (M) x 4 (N); warp tile 64x32; mma m16n8k16.
// ---------------------------------------------------------------------------
__global__ void __launch_bounds__(256) gemm_mma_kernel(
    const float* __restrict__ x, int N,
    const float* __restrict__ Wk, const float* __restrict__ bk,
    const float* __restrict__ Wq, const float* __restrict__ bq,
    const float* __restrict__ Wv, const float* __restrict__ bv,
    const float* __restrict__ Wsk, const float* __restrict__ bsk,
    float* __restrict__ out)
{
    extern __shared__ __nv_bfloat16 sm[];
    const uint32_t sbase = smem_u32(sm);

    const float* W; const float* b; float* dst;
    switch (blockIdx.y) {
        case 0:  W = Wk;  b = bk;  dst = g_K; break;
        case 1:  W = Wq;  b = bq;  dst = g_Q; break;
        case 2:  W = Wv;  b = bv;  dst = g_V; break;
        default: W = Wsk; b = bsk; dst = out; break;
    }

    const int tid  = threadIdx.x;
    const int wid  = tid >> 5;
    const int lane = tid & 31;
    const int m0   = blockIdx.x * TILE_M;
    const int rem  = N - m0;

    // ---- Load A = x tile [128 x 128] fp32 -> bf16 hi/lo ----
    {
        const float4* x4 = (const float4*)(x + (size_t)m0 * D);
        #pragma unroll
        for (int i = 0; i < 16; i++) {
            int idx = tid + 256 * i;
            int row = idx >> 5;
            int k4  = (idx & 31) << 2;
            float4 v = make_float4(0.f, 0.f, 0.f, 0.f);
            if (row < rem) v = x4[idx];
            uint2 hi = make_uint2(pack2(v.x, v.y), pack2(v.z, v.w));
            uint2 lo = make_uint2(pack2(bf16_residual(v.x), bf16_residual(v.y)),
                                  pack2(bf16_residual(v.z), bf16_residual(v.w)));
            int e = row * ASTRIDE + k4;
            *(uint2*)(sm + SM_A_HI + e) = hi;
            *(uint2*)(sm + SM_A_LO + e) = lo;
        }
    }
    // ---- Load B[n][k] = W[k][n] (transposed), bf16 hi/lo ----
    {
        #pragma unroll
        for (int j = 0; j < 16; j++) {
            int c  = wid + 8 * j;              // 128 chunks
            int n  = ((c >> 5) << 5) + lane;   // coalesced over lanes
            int k0 = (c & 31) << 2;
            float w0 = W[(size_t)(k0 + 0) * D + n];
            float w1 = W[(size_t)(k0 + 1) * D + n];
            float w2 = W[(size_t)(k0 + 2) * D + n];
            float w3 = W[(size_t)(k0 + 3) * D + n];
            uint2 hi = make_uint2(pack2(w0, w1), pack2(w2, w3));
            uint2 lo = make_uint2(pack2(bf16_residual(w0), bf16_residual(w1)),
                                  pack2(bf16_residual(w2), bf16_residual(w3)));
            int e = n * ASTRIDE + k0;
            *(uint2*)(sm + SM_B_HI + e) = hi;
            *(uint2*)(sm + SM_B_LO + e) = lo;
        }
    }
    __syncthreads();

    // ---- Warp tiling: wm in {0,1} (64 rows), wn in {0..3} (32 cols) ----
    const int wm = wid & 1;
    const int wn = wid >> 1;
    const int mw = wm << 6;     // warp row base
    const int nw = wn << 5;     // warp col base

    float acc[4][4][4];
    #pragma unroll
    for (int i = 0; i < 4; i++)
        #pragma unroll
        for (int j = 0; j < 4; j++)
            #pragma unroll
            for (int k = 0; k < 4; k++) acc[i][j][k] = 0.f;

    // ldmatrix lane address components
    const int arow = lane & 15;           // A: row within 16
    const int acol = (lane >> 4) << 3;    // A: k-offset 0 or 8
    const int brow = lane & 7;            // B: n within 8
    const int bcol = ((lane >> 3) & 1) << 3;  // B: k-offset 0 or 8

    #pragma unroll
    for (int ks = 0; ks < 8; ks++) {
        const int kk = ks << 4;
        uint32_t ah[4][4], al[4][4], bh[4][2], bl[4][2];
        #pragma unroll
        for (int mt = 0; mt < 4; mt++) {
            uint32_t off = (uint32_t)((mw + (mt << 4) + arow) * ASTRIDE + kk + acol) * 2;
            ldsm_x4(ah[mt], sbase + SM_A_HI * 2 + off);
            ldsm_x4(al[mt], sbase + SM_A_LO * 2 + off);
        }
        #pragma unroll
        for (int nt = 0; nt < 4; nt++) {
            uint32_t off = (uint32_t)((nw + (nt << 3) + brow) * ASTRIDE + kk + bcol) * 2;
            ldsm_x2(bh[nt], sbase + SM_B_HI * 2 + off);
            ldsm_x2(bl[nt], sbase + SM_B_LO * 2 + off);
        }
        #pragma unroll
        for (int mt = 0; mt < 4; mt++)
            #pragma unroll
            for (int nt = 0; nt < 4; nt++) {
                mma16816(acc[mt][nt], ah[mt], bh[nt]);
                mma16816(acc[mt][nt], ah[mt], bl[nt]);
                mma16816(acc[mt][nt], al[mt], bh[nt]);
            }
    }

    // ---- Epilogue: add bias, store fp32 ----
    {
        const int gid = lane >> 2;   // 0..7
        const int tg  = lane & 3;    // 0..3
        #pragma unroll
        for (int mt = 0; mt < 4; mt++) {
            #pragma unroll
            for (int nt = 0; nt < 4; nt++) {
                int col = nw + (nt << 3) + (tg << 1);
                float2 bb = *(const float2*)(b + col);
                int r0 = mw + (mt << 4) + gid;
                int r1 = r0 + 8;
                if (m0 + r0 < N) {
                    float2 v; v.x = acc[mt][nt][0] + bb.x; v.y = acc[mt][nt][1] + bb.y;
                    *(float2*)(dst + (size_t)(m0 + r0) * D + col) = v;
                }
                if (m0 + r1 < N) {
                    float2 v; v.x = acc[mt][nt][2] + bb.x; v.y = acc[mt][nt][3] + bb.y;
                    *(float2*)(dst + (size_t)(m0 + r1) * D + col) = v;
                }
            }
        }
    }
}

// ---------------------------------------------------------------------------
// Edge kernel: one warp per edge. lane c handles channels [4c, 4c+3].
// ---------------------------------------------------------------------------
__global__ void __launch_bounds__(256) edge_kernel(
    const void* __restrict__ ei_raw, int E, float* __restrict__ out)
{
    const int warp = (blockIdx.x * blockDim.x + threadIdx.x) >> 5;
    const int lane = threadIdx.x & 31;
    if (warp >= E) return;

    int src, dst;
    if (g_is64) {
        const long long* e64 = (const long long*)ei_raw;
        src = (int)e64[warp];
        dst = (int)e64[(size_t)E + warp];
    } else {
        const int* e32 = (const int*)ei_raw;
        src = e32[warp];
        dst = e32[(size_t)E + warp];
    }

    const float4 kd = ((const float4*)g_K)[(size_t)dst * D4 + lane];
    const float4 qs = ((const float4*)g_Q)[(size_t)src * D4 + lane];
    const float4 vs = ((const float4*)g_V)[(size_t)src * D4 + lane];

    float4 m;
    m.x = vs.x * __fdividef(1.f, 1.f + __expf(-(kd.x + qs.x)));
    m.y = vs.y * __fdividef(1.f, 1.f + __expf(-(kd.y + qs.y)));
    m.z = vs.z * __fdividef(1.f, 1.f + __expf(-(kd.z + qs.z)));
    m.w = vs.w * __fdividef(1.f, 1.f + __expf(-(kd.w + qs.w)));

    float* p = out + (size_t)dst * D + lane * 4;
    asm volatile("red.global.add.v4.f32 [%0], {%1, %2, %3, %4};"
                 :: "l"(p), "f"(m.x), "f"(m.y), "f"(m.z), "f"(m.w)
                 : "memory");
}

// ---------------------------------------------------------------------------
extern "C" void kernel_launch(void* const* d_in, const int* in_sizes, int n_in,
                              void* d_out, int out_size)
{
    const float* x    = (const float*)d_in[0];
    const void*  ei   = d_in[1];
    const float* Wk   = (const float*)d_in[3];
    const float* bk   = (const float*)d_in[4];
    const float* Wq   = (const float*)d_in[5];
    const float* bq   = (const float*)d_in[6];
    const float* Wv   = (const float*)d_in[7];
    const float* bv   = (const float*)d_in[8];
    const float* Wsk  = (const float*)d_in[9];
    const float* bias = (const float*)d_in[10];
    float* out = (float*)d_out;

    const int N = in_sizes[0] / D;
    const int E = in_sizes[1] / 2;

    detect_dtype_kernel<<<1, 1>>>((const int*)ei);

    cudaFuncSetAttribute(gemm_mma_kernel,
                         cudaFuncAttributeMaxDynamicSharedMemorySize, SM_BYTES);
    dim3 ggrid((N + TILE_M - 1) / TILE_M, 4);
    gemm_mma_kernel<<<ggrid, 256, SM_BYTES>>>(
        x, N, Wk, bk, Wq, bq, Wv, bv, Wsk, bias, out);

    const int eblocks = (E + 7) / 8;   // 8 warps per 256-thread block
    edge_kernel<<<eblocks, 256>>>(ei, E, out);
}